// round 1
// baseline (speedup 1.0000x reference)
#include <cuda_runtime.h>
#include <cstdint>

#define B 16
#define P 512          // m = n = 512
#define D 128
#define ITERS 20

// ---------------- device scratch (allocation-free rule: __device__ globals) --
__device__ float g_qm[(size_t)B * P * P];   // 16 MB, (b, j, i) row-major, i contiguous
__device__ float g_ra[B * P];               // ||u_i||^2 (cur)
__device__ float g_rb[B * P];               // ||v_j||^2 (nxt)
__device__ float g_qsq[B];                  // sum qm^2 per batch (for lr)

// ---------------- helpers ----------------------------------------------------
__device__ __forceinline__ float wred(float v) {
    v += __shfl_xor_sync(0xffffffffu, v, 16);
    v += __shfl_xor_sync(0xffffffffu, v, 8);
    v += __shfl_xor_sync(0xffffffffu, v, 4);
    v += __shfl_xor_sync(0xffffffffu, v, 2);
    v += __shfl_xor_sync(0xffffffffu, v, 1);
    return v;
}

__device__ __forceinline__ void cluster_sync_all() {
    asm volatile("barrier.cluster.arrive.aligned;" ::: "memory");
    asm volatile("barrier.cluster.wait.aligned;" ::: "memory");
}

__device__ __forceinline__ uint32_t smem_u32(const void* p) {
    return (uint32_t)__cvta_generic_to_shared(p);
}

__device__ __forceinline__ float dsmem_ld_f32(uint32_t laddr, uint32_t rank) {
    uint32_t raddr; float v;
    asm volatile("mapa.shared::cluster.u32 %0, %1, %2;" : "=r"(raddr) : "r"(laddr), "r"(rank));
    asm volatile("ld.shared::cluster.f32 %0, [%1];" : "=f"(v) : "r"(raddr) : "memory");
    return v;
}

// ---------------- kernel 1: row norms + qsq zero ------------------------------
// ra[b,i] = ||ncur_i||^2 + ||ecur_i||^2 ; rb[b,j] = ||nnxt_j||^2 + ||enxt_j||^2
__global__ void norms_kernel(const float* __restrict__ ncur, const float* __restrict__ ecur,
                             const float* __restrict__ nnxt, const float* __restrict__ enxt) {
    int gw = blockIdx.x * (blockDim.x >> 5) + (threadIdx.x >> 5);   // global warp = row id in [0, 8192)
    int l  = threadIdx.x & 31;
    size_t base = (size_t)gw * D;   // gw = b*512 + i

    float4 a1 = ((const float4*)(ncur + base))[l];
    float4 a2 = ((const float4*)(ecur + base))[l];
    float4 b1 = ((const float4*)(nnxt + base))[l];
    float4 b2 = ((const float4*)(enxt + base))[l];

    float sa = a1.x*a1.x + a1.y*a1.y + a1.z*a1.z + a1.w*a1.w
             + a2.x*a2.x + a2.y*a2.y + a2.z*a2.z + a2.w*a2.w;
    float sb = b1.x*b1.x + b1.y*b1.y + b1.z*b1.z + b1.w*b1.w
             + b2.x*b2.x + b2.y*b2.y + b2.z*b2.z + b2.w*b2.w;
    sa = wred(sa);
    sb = wred(sb);
    if (l == 0) { g_ra[gw] = sa; g_rb[gw] = sb; }
    if (blockIdx.x == 0 && threadIdx.x < B) g_qsq[threadIdx.x] = 0.f;
}

// ---------------- kernel 2: gram / cost matrix --------------------------------
// qm[b, j, i] = 0.5*(ra_i + rb_j) - (ncur_i.nnxt_j + ecur_i.enxt_j)
// 64x64 tile per block, 256 threads, 4x4 micro-tile, k-major SMEM for vector LDS.
__global__ __launch_bounds__(256) void gram_kernel(
    const float* __restrict__ ncur, const float* __restrict__ ecur,
    const float* __restrict__ nnxt, const float* __restrict__ enxt) {

    __shared__ float Us[64][68];   // Us[k][i]  (k-major, padded, 16B-aligned rows)
    __shared__ float Vs[64][68];   // Vs[k][j]
    __shared__ float sQred[8];

    const int b  = blockIdx.z;
    const int i0 = blockIdx.x * 64;
    const int j0 = blockIdx.y * 64;
    const int tid = threadIdx.x;
    const int tx = tid & 15;       // i micro
    const int ty = tid >> 4;       // j micro

    float acc[4][4] = {};

    const int row = tid >> 2;      // 0..63  (loader row)
    const int kq  = tid & 3;       // 0..3   (16 floats each)

    for (int kc = 0; kc < 4; kc++) {
        const float* usrc = ((kc & 2) ? ecur : ncur) + (size_t)b * (P * D) + (kc & 1) * 64;
        const float* vsrc = ((kc & 2) ? enxt : nnxt) + (size_t)b * (P * D) + (kc & 1) * 64;

        const float4* up = (const float4*)(usrc + (size_t)(i0 + row) * D) + kq * 4;
        const float4* vp = (const float4*)(vsrc + (size_t)(j0 + row) * D) + kq * 4;
        float4 ur[4], vr[4];
        #pragma unroll
        for (int q = 0; q < 4; q++) { ur[q] = up[q]; vr[q] = vp[q]; }

        __syncthreads();   // previous chunk's compute done
        #pragma unroll
        for (int q = 0; q < 4; q++) {
            int kk = kq * 16 + q * 4;
            Us[kk+0][row] = ur[q].x; Us[kk+1][row] = ur[q].y;
            Us[kk+2][row] = ur[q].z; Us[kk+3][row] = ur[q].w;
            Vs[kk+0][row] = vr[q].x; Vs[kk+1][row] = vr[q].y;
            Vs[kk+2][row] = vr[q].z; Vs[kk+3][row] = vr[q].w;
        }
        __syncthreads();

        #pragma unroll 16
        for (int k = 0; k < 64; k++) {
            float4 u4 = *(const float4*)&Us[k][tx * 4];
            float4 v4 = *(const float4*)&Vs[k][ty * 4];
            float uu[4] = {u4.x, u4.y, u4.z, u4.w};
            float vv[4] = {v4.x, v4.y, v4.z, v4.w};
            #pragma unroll
            for (int r = 0; r < 4; r++)
                #pragma unroll
                for (int c = 0; c < 4; c++)
                    acc[r][c] += vv[r] * uu[c];
        }
    }

    // epilogue: qm = 0.5*(ra+rb) - acc ; accumulate qsq
    float raL[4], rbL[4];
    #pragma unroll
    for (int c = 0; c < 4; c++) raL[c] = g_ra[b * P + i0 + tx * 4 + c];
    #pragma unroll
    for (int r = 0; r < 4; r++) rbL[r] = g_rb[b * P + j0 + ty * 4 + r];

    float qs = 0.f;
    #pragma unroll
    for (int r = 0; r < 4; r++) {
        float4 o;
        o.x = 0.5f * (raL[0] + rbL[r]) - acc[r][0];
        o.y = 0.5f * (raL[1] + rbL[r]) - acc[r][1];
        o.z = 0.5f * (raL[2] + rbL[r]) - acc[r][2];
        o.w = 0.5f * (raL[3] + rbL[r]) - acc[r][3];
        qs += o.x*o.x + o.y*o.y + o.z*o.z + o.w*o.w;
        *(float4*)&g_qm[((size_t)b * P + j0 + ty * 4 + r) * P + i0 + tx * 4] = o;
    }
    qs = wred(qs);
    if ((tid & 31) == 0) sQred[tid >> 5] = qs;
    __syncthreads();
    if (tid == 0) {
        float t = 0.f;
        #pragma unroll
        for (int w = 0; w < 8; w++) t += sQred[w];
        atomicAdd(&g_qsq[b], t);
    }
}

// ---------------- kernel 3: persistent cluster QP solve -----------------------
// cluster of 8 CTAs per batch; each CTA owns 64 rows of X in SMEM.
// Lazy column scaling: sScale holds last iteration's col scale, folded into reads.
#define QP_SMEM_FLOATS (32768 + 512 + 512 + 16 + 16)
#define QP_SMEM_BYTES  (QP_SMEM_FLOATS * 4)

__global__ void __cluster_dims__(8, 1, 1) __launch_bounds__(512, 1)
qp_kernel(float* __restrict__ out) {
    extern __shared__ float sm[];
    float*  sX      = sm;                       // 64*512
    float*  sScale  = sm + 32768;               // 512 (col scale, lazy)
    float*  sC      = sm + 32768 + 512;         // 512 (col-sum partials)
    float*  sRed    = sm + 32768 + 1024;        // 16
    float*  sS      = sm + 32768 + 1024 + 16;   // 1 (partial s)

    float4* sX4  = (float4*)sX;
    float4* sSc4 = (float4*)sScale;

    uint32_t rank;
    asm("mov.u32 %0, %%cluster_ctarank;" : "=r"(rank));
    const int b   = blockIdx.x >> 3;
    const int tid = threadIdx.x;

    const float lr = 0.5f / (g_qsq[b] + 1e-8f);
    const float4* qm4 = (const float4*)(g_qm + ((size_t)b * P + rank * 64) * P);  // 8192 float4

    // init: X = 1/512, scale = 1
    const float4 iv = make_float4(1.f/512, 1.f/512, 1.f/512, 1.f/512);
    for (int idx = tid; idx < 8192; idx += 512) sX4[idx] = iv;
    if (tid < 128) sSc4[tid] = make_float4(1.f, 1.f, 1.f, 1.f);
    __syncthreads();

    const uint32_t sS_a = smem_u32(sS);
    const uint32_t sC_a = smem_u32(sC);
    const int w = tid >> 5, l = tid & 31;

    for (int it = 0; it < ITERS; it++) {
        // ---- pass 1: partial s = sum(qm * X*scale) over own rows
        float part = 0.f;
        for (int idx = tid; idx < 8192; idx += 512) {
            float4 q = qm4[idx];
            float4 x = sX4[idx];
            float4 sc = sSc4[idx & 127];
            part += q.x*(x.x*sc.x) + q.y*(x.y*sc.y) + q.z*(x.z*sc.z) + q.w*(x.w*sc.w);
        }
        part = wred(part);
        if (l == 0) sRed[w] = part;
        __syncthreads();
        if (tid < 32) {
            float v = (tid < 16) ? sRed[tid] : 0.f;
            v = wred(v);
            if (tid == 0) sS[0] = v;
        }
        cluster_sync_all();                      // #1

        float s = 0.f;
        #pragma unroll
        for (uint32_t r = 0; r < 8; r++) s += dsmem_ld_f32(sS_a, r);
        const float cq = 2.f * lr * s;

        // ---- pass 2a: gradient + clip + row-normalize (warp = 4 rows)
        #pragma unroll
        for (int q = 0; q < 4; q++) {
            const int jl = w * 4 + q;
            const float4* qrow = qm4 + jl * 128;
            float4* xrow = sX4 + jl * 128;
            float4 xn[4];
            float rs = 0.f;
            #pragma unroll
            for (int t = 0; t < 4; t++) {
                int c4 = l + 32 * t;
                float4 x = xrow[c4], sc = sSc4[c4], qv = qrow[c4];
                float4 v;
                v.x = fminf(fmaxf(x.x*sc.x - cq*qv.x, 0.f), 1.f);
                v.y = fminf(fmaxf(x.y*sc.y - cq*qv.y, 0.f), 1.f);
                v.z = fminf(fmaxf(x.z*sc.z - cq*qv.z, 0.f), 1.f);
                v.w = fminf(fmaxf(x.w*sc.w - cq*qv.w, 0.f), 1.f);
                xn[t] = v;
                rs += v.x + v.y + v.z + v.w;
            }
            rs = wred(rs);
            const float inv = 1.f / (rs + 1e-8f);
            #pragma unroll
            for (int t = 0; t < 4; t++) {
                float4 v = xn[t];
                v.x *= inv; v.y *= inv; v.z *= inv; v.w *= inv;
                xrow[l + 32 * t] = v;
            }
        }
        __syncthreads();

        // ---- pass 2b: per-CTA column sums (row-normalized X)
        if (tid < 128) {
            float4 cs = make_float4(0.f, 0.f, 0.f, 0.f);
            #pragma unroll 8
            for (int j = 0; j < 64; j++) {
                float4 x = sX4[j * 128 + tid];
                cs.x += x.x; cs.y += x.y; cs.z += x.z; cs.w += x.w;
            }
            ((float4*)sC)[tid] = cs;
        }
        cluster_sync_all();                      // #2

        // ---- total col sum over cluster, new lazy scale
        {
            float tot = 0.f;
            #pragma unroll
            for (uint32_t r = 0; r < 8; r++) tot += dsmem_ld_f32(sC_a + tid * 4, r);
            sScale[tid] = fminf(1.f, 2.f / (tot + 1e-8f));
        }
        __syncthreads();
    }

    // ---- writeout: apply final col scale
    float4* out4 = (float4*)out + ((size_t)b * P + rank * 64) * 128;
    for (int idx = tid; idx < 8192; idx += 512) {
        float4 x = sX4[idx], sc = sSc4[idx & 127];
        out4[idx] = make_float4(x.x*sc.x, x.y*sc.y, x.z*sc.z, x.w*sc.w);
    }
}

// ---------------- launch -------------------------------------------------------
extern "C" void kernel_launch(void* const* d_in, const int* in_sizes, int n_in,
                              void* d_out, int out_size) {
    (void)in_sizes; (void)n_in; (void)out_size;
    const float* ncur = (const float*)d_in[0];
    const float* ecur = (const float*)d_in[1];
    const float* nnxt = (const float*)d_in[2];
    const float* enxt = (const float*)d_in[3];
    float* out = (float*)d_out;

    cudaFuncSetAttribute(qp_kernel, cudaFuncAttributeMaxDynamicSharedMemorySize, QP_SMEM_BYTES);

    norms_kernel<<<1024, 256>>>(ncur, ecur, nnxt, enxt);
    gram_kernel<<<dim3(8, 8, B), 256>>>(ncur, ecur, nnxt, enxt);
    qp_kernel<<<128, 512, QP_SMEM_BYTES>>>(out);
}

// round 2
// speedup vs baseline: 1.0059x; 1.0059x over previous
#include <cuda_runtime.h>
#include <cstdint>

#define B 16
#define P 512          // m = n = 512
#define D 128
#define ITERS 20

// ---------------- device scratch (allocation-free rule: __device__ globals) --
__device__ float g_qm[(size_t)B * P * P];   // 16 MB, (b, j, i) row-major, i contiguous
__device__ float g_ra[B * P];               // ||u_i||^2 (cur)
__device__ float g_rb[B * P];               // ||v_j||^2 (nxt)
__device__ float g_qsq[B];                  // sum qm^2 per batch (for lr)

// ---------------- helpers ----------------------------------------------------
__device__ __forceinline__ float wred(float v) {
    v += __shfl_xor_sync(0xffffffffu, v, 16);
    v += __shfl_xor_sync(0xffffffffu, v, 8);
    v += __shfl_xor_sync(0xffffffffu, v, 4);
    v += __shfl_xor_sync(0xffffffffu, v, 2);
    v += __shfl_xor_sync(0xffffffffu, v, 1);
    return v;
}

__device__ __forceinline__ void cluster_sync_all() {
    asm volatile("barrier.cluster.arrive.aligned;" ::: "memory");
    asm volatile("barrier.cluster.wait.aligned;" ::: "memory");
}

__device__ __forceinline__ uint32_t smem_u32(const void* p) {
    return (uint32_t)__cvta_generic_to_shared(p);
}

__device__ __forceinline__ float dsmem_ld_f32(uint32_t laddr, uint32_t rank) {
    uint32_t raddr; float v;
    asm volatile("mapa.shared::cluster.u32 %0, %1, %2;" : "=r"(raddr) : "r"(laddr), "r"(rank));
    asm volatile("ld.shared::cluster.f32 %0, [%1];" : "=f"(v) : "r"(raddr) : "memory");
    return v;
}

// ---------------- kernel 1: row norms + qsq zero ------------------------------
// ra[b,i] = ||ncur_i||^2 + ||ecur_i||^2 ; rb[b,j] = ||nnxt_j||^2 + ||enxt_j||^2
__global__ void norms_kernel(const float* __restrict__ ncur, const float* __restrict__ ecur,
                             const float* __restrict__ nnxt, const float* __restrict__ enxt) {
    int gw = blockIdx.x * (blockDim.x >> 5) + (threadIdx.x >> 5);   // global warp = row id in [0, 8192)
    int l  = threadIdx.x & 31;
    size_t base = (size_t)gw * D;   // gw = b*512 + i

    float4 a1 = ((const float4*)(ncur + base))[l];
    float4 a2 = ((const float4*)(ecur + base))[l];
    float4 b1 = ((const float4*)(nnxt + base))[l];
    float4 b2 = ((const float4*)(enxt + base))[l];

    float sa = a1.x*a1.x + a1.y*a1.y + a1.z*a1.z + a1.w*a1.w
             + a2.x*a2.x + a2.y*a2.y + a2.z*a2.z + a2.w*a2.w;
    float sb = b1.x*b1.x + b1.y*b1.y + b1.z*b1.z + b1.w*b1.w
             + b2.x*b2.x + b2.y*b2.y + b2.z*b2.z + b2.w*b2.w;
    sa = wred(sa);
    sb = wred(sb);
    if (l == 0) { g_ra[gw] = sa; g_rb[gw] = sb; }
    if (blockIdx.x == 0 && threadIdx.x < B) g_qsq[threadIdx.x] = 0.f;
}

// ---------------- kernel 2: gram / cost matrix --------------------------------
// qm[b, j, i] = 0.5*(ra_i + rb_j) - (ncur_i.nnxt_j + ecur_i.enxt_j)
// 64x64 tile per block, 256 threads, 4x4 micro-tile, k-major SMEM for vector LDS.
__global__ __launch_bounds__(256) void gram_kernel(
    const float* __restrict__ ncur, const float* __restrict__ ecur,
    const float* __restrict__ nnxt, const float* __restrict__ enxt) {

    __shared__ float Us[64][68];   // Us[k][i]  (k-major, padded, 16B-aligned rows)
    __shared__ float Vs[64][68];   // Vs[k][j]
    __shared__ float sQred[8];

    const int b  = blockIdx.z;
    const int i0 = blockIdx.x * 64;
    const int j0 = blockIdx.y * 64;
    const int tid = threadIdx.x;
    const int tx = tid & 15;       // i micro
    const int ty = tid >> 4;       // j micro

    float acc[4][4] = {};

    const int row = tid >> 2;      // 0..63  (loader row)
    const int kq  = tid & 3;       // 0..3   (16 floats each)

    for (int kc = 0; kc < 4; kc++) {
        const float* usrc = ((kc & 2) ? ecur : ncur) + (size_t)b * (P * D) + (kc & 1) * 64;
        const float* vsrc = ((kc & 2) ? enxt : nnxt) + (size_t)b * (P * D) + (kc & 1) * 64;

        const float4* up = (const float4*)(usrc + (size_t)(i0 + row) * D) + kq * 4;
        const float4* vp = (const float4*)(vsrc + (size_t)(j0 + row) * D) + kq * 4;
        float4 ur[4], vr[4];
        #pragma unroll
        for (int q = 0; q < 4; q++) { ur[q] = up[q]; vr[q] = vp[q]; }

        __syncthreads();   // previous chunk's compute done
        #pragma unroll
        for (int q = 0; q < 4; q++) {
            int kk = kq * 16 + q * 4;
            Us[kk+0][row] = ur[q].x; Us[kk+1][row] = ur[q].y;
            Us[kk+2][row] = ur[q].z; Us[kk+3][row] = ur[q].w;
            Vs[kk+0][row] = vr[q].x; Vs[kk+1][row] = vr[q].y;
            Vs[kk+2][row] = vr[q].z; Vs[kk+3][row] = vr[q].w;
        }
        __syncthreads();

        #pragma unroll 16
        for (int k = 0; k < 64; k++) {
            float4 u4 = *(const float4*)&Us[k][tx * 4];
            float4 v4 = *(const float4*)&Vs[k][ty * 4];
            float uu[4] = {u4.x, u4.y, u4.z, u4.w};
            float vv[4] = {v4.x, v4.y, v4.z, v4.w};
            #pragma unroll
            for (int r = 0; r < 4; r++)
                #pragma unroll
                for (int c = 0; c < 4; c++)
                    acc[r][c] += vv[r] * uu[c];
        }
    }

    // epilogue: qm = 0.5*(ra+rb) - acc ; accumulate qsq
    float raL[4], rbL[4];
    #pragma unroll
    for (int c = 0; c < 4; c++) raL[c] = g_ra[b * P + i0 + tx * 4 + c];
    #pragma unroll
    for (int r = 0; r < 4; r++) rbL[r] = g_rb[b * P + j0 + ty * 4 + r];

    float qs = 0.f;
    #pragma unroll
    for (int r = 0; r < 4; r++) {
        float4 o;
        o.x = 0.5f * (raL[0] + rbL[r]) - acc[r][0];
        o.y = 0.5f * (raL[1] + rbL[r]) - acc[r][1];
        o.z = 0.5f * (raL[2] + rbL[r]) - acc[r][2];
        o.w = 0.5f * (raL[3] + rbL[r]) - acc[r][3];
        qs += o.x*o.x + o.y*o.y + o.z*o.z + o.w*o.w;
        *(float4*)&g_qm[((size_t)b * P + j0 + ty * 4 + r) * P + i0 + tx * 4] = o;
    }
    qs = wred(qs);
    if ((tid & 31) == 0) sQred[tid >> 5] = qs;
    __syncthreads();
    if (tid == 0) {
        float t = 0.f;
        #pragma unroll
        for (int w = 0; w < 8; w++) t += sQred[w];
        atomicAdd(&g_qsq[b], t);
    }
}

// ---------------- kernel 3: persistent cluster QP solve -----------------------
// cluster of 8 CTAs per batch; each CTA owns 64 rows of X in SMEM.
// Lazy column scaling: sScale holds last iteration's col scale, folded into reads.
#define QP_SMEM_FLOATS (32768 + 512 + 512 + 16 + 16)
#define QP_SMEM_BYTES  (QP_SMEM_FLOATS * 4)

__global__ void __cluster_dims__(8, 1, 1) __launch_bounds__(512, 1)
qp_kernel(float* __restrict__ out) {
    extern __shared__ float sm[];
    float*  sX      = sm;                       // 64*512
    float*  sScale  = sm + 32768;               // 512 (col scale, lazy)
    float*  sC      = sm + 32768 + 512;         // 512 (col-sum partials)
    float*  sRed    = sm + 32768 + 1024;        // 16
    float*  sS      = sm + 32768 + 1024 + 16;   // 1 (partial s)

    float4* sX4  = (float4*)sX;
    float4* sSc4 = (float4*)sScale;

    uint32_t rank;
    asm("mov.u32 %0, %%cluster_ctarank;" : "=r"(rank));
    const int b   = blockIdx.x >> 3;
    const int tid = threadIdx.x;

    const float lr = 0.5f / (g_qsq[b] + 1e-8f);
    const float4* qm4 = (const float4*)(g_qm + ((size_t)b * P + rank * 64) * P);  // 8192 float4

    // init: X = 1/512, scale = 1
    const float4 iv = make_float4(1.f/512, 1.f/512, 1.f/512, 1.f/512);
    for (int idx = tid; idx < 8192; idx += 512) sX4[idx] = iv;
    if (tid < 128) sSc4[tid] = make_float4(1.f, 1.f, 1.f, 1.f);
    __syncthreads();

    const uint32_t sS_a = smem_u32(sS);
    const uint32_t sC_a = smem_u32(sC);
    const int w = tid >> 5, l = tid & 31;

    for (int it = 0; it < ITERS; it++) {
        // ---- pass 1: partial s = sum(qm * X*scale) over own rows
        float part = 0.f;
        for (int idx = tid; idx < 8192; idx += 512) {
            float4 q = qm4[idx];
            float4 x = sX4[idx];
            float4 sc = sSc4[idx & 127];
            part += q.x*(x.x*sc.x) + q.y*(x.y*sc.y) + q.z*(x.z*sc.z) + q.w*(x.w*sc.w);
        }
        part = wred(part);
        if (l == 0) sRed[w] = part;
        __syncthreads();
        if (tid < 32) {
            float v = (tid < 16) ? sRed[tid] : 0.f;
            v = wred(v);
            if (tid == 0) sS[0] = v;
        }
        cluster_sync_all();                      // #1

        float s = 0.f;
        #pragma unroll
        for (uint32_t r = 0; r < 8; r++) s += dsmem_ld_f32(sS_a, r);
        const float cq = 2.f * lr * s;

        // ---- pass 2a: gradient + clip + row-normalize (warp = 4 rows)
        #pragma unroll
        for (int q = 0; q < 4; q++) {
            const int jl = w * 4 + q;
            const float4* qrow = qm4 + jl * 128;
            float4* xrow = sX4 + jl * 128;
            float4 xn[4];
            float rs = 0.f;
            #pragma unroll
            for (int t = 0; t < 4; t++) {
                int c4 = l + 32 * t;
                float4 x = xrow[c4], sc = sSc4[c4], qv = qrow[c4];
                float4 v;
                v.x = fminf(fmaxf(x.x*sc.x - cq*qv.x, 0.f), 1.f);
                v.y = fminf(fmaxf(x.y*sc.y - cq*qv.y, 0.f), 1.f);
                v.z = fminf(fmaxf(x.z*sc.z - cq*qv.z, 0.f), 1.f);
                v.w = fminf(fmaxf(x.w*sc.w - cq*qv.w, 0.f), 1.f);
                xn[t] = v;
                rs += v.x + v.y + v.z + v.w;
            }
            rs = wred(rs);
            const float inv = 1.f / (rs + 1e-8f);
            #pragma unroll
            for (int t = 0; t < 4; t++) {
                float4 v = xn[t];
                v.x *= inv; v.y *= inv; v.z *= inv; v.w *= inv;
                xrow[l + 32 * t] = v;
            }
        }
        __syncthreads();

        // ---- pass 2b: per-CTA column sums (row-normalized X)
        if (tid < 128) {
            float4 cs = make_float4(0.f, 0.f, 0.f, 0.f);
            #pragma unroll 8
            for (int j = 0; j < 64; j++) {
                float4 x = sX4[j * 128 + tid];
                cs.x += x.x; cs.y += x.y; cs.z += x.z; cs.w += x.w;
            }
            ((float4*)sC)[tid] = cs;
        }
        cluster_sync_all();                      // #2

        // ---- total col sum over cluster, new lazy scale
        {
            float tot = 0.f;
            #pragma unroll
            for (uint32_t r = 0; r < 8; r++) tot += dsmem_ld_f32(sC_a + tid * 4, r);
            sScale[tid] = fminf(1.f, 2.f / (tot + 1e-8f));
        }
        __syncthreads();
    }

    // ---- writeout: apply final col scale
    float4* out4 = (float4*)out + ((size_t)b * P + rank * 64) * 128;
    for (int idx = tid; idx < 8192; idx += 512) {
        float4 x = sX4[idx], sc = sSc4[idx & 127];
        out4[idx] = make_float4(x.x*sc.x, x.y*sc.y, x.z*sc.z, x.w*sc.w);
    }
}

// ---------------- launch -------------------------------------------------------
extern "C" void kernel_launch(void* const* d_in, const int* in_sizes, int n_in,
                              void* d_out, int out_size) {
    (void)in_sizes; (void)n_in; (void)out_size;
    const float* ncur = (const float*)d_in[0];
    const float* ecur = (const float*)d_in[1];
    const float* nnxt = (const float*)d_in[2];
    const float* enxt = (const float*)d_in[3];
    float* out = (float*)d_out;

    cudaFuncSetAttribute(qp_kernel, cudaFuncAttributeMaxDynamicSharedMemorySize, QP_SMEM_BYTES);

    norms_kernel<<<1024, 256>>>(ncur, ecur, nnxt, enxt);
    gram_kernel<<<dim3(8, 8, B), 256>>>(ncur, ecur, nnxt, enxt);
    qp_kernel<<<128, 512, QP_SMEM_BYTES>>>(out);
}

// round 3
// speedup vs baseline: 1.0560x; 1.0499x over previous
#include <cuda_runtime.h>
#include <cstdint>

#define B 16
#define P 512          // m = n = 512
#define D 128
#define ITERS 20

// ---------------- device scratch (allocation-free rule: __device__ globals) --
__device__ float g_qm[(size_t)B * P * P];   // 16 MB, (b, j, i) row-major, i contiguous
__device__ float g_ra[B * P];               // ||u_i||^2 (cur)
__device__ float g_rb[B * P];               // ||v_j||^2 (nxt)
__device__ float g_qsq[B];                  // sum qm^2 per batch (for lr)
__device__ float g_qsum[B];                 // sum qm per batch (for s0)

// ---------------- helpers ----------------------------------------------------
__device__ __forceinline__ float wred(float v) {
    v += __shfl_xor_sync(0xffffffffu, v, 16);
    v += __shfl_xor_sync(0xffffffffu, v, 8);
    v += __shfl_xor_sync(0xffffffffu, v, 4);
    v += __shfl_xor_sync(0xffffffffu, v, 2);
    v += __shfl_xor_sync(0xffffffffu, v, 1);
    return v;
}

__device__ __forceinline__ void cluster_sync_all() {
    asm volatile("barrier.cluster.arrive.aligned;" ::: "memory");
    asm volatile("barrier.cluster.wait.aligned;" ::: "memory");
}

__device__ __forceinline__ uint32_t smem_u32(const void* p) {
    return (uint32_t)__cvta_generic_to_shared(p);
}

__device__ __forceinline__ float dsmem_ld_f32(uint32_t laddr, uint32_t rank) {
    uint32_t raddr; float v;
    asm volatile("mapa.shared::cluster.u32 %0, %1, %2;" : "=r"(raddr) : "r"(laddr), "r"(rank));
    asm volatile("ld.shared::cluster.f32 %0, [%1];" : "=f"(v) : "r"(raddr) : "memory");
    return v;
}

__device__ __forceinline__ void dsmem_st_f32(uint32_t laddr, uint32_t rank, float v) {
    uint32_t raddr;
    asm volatile("mapa.shared::cluster.u32 %0, %1, %2;" : "=r"(raddr) : "r"(laddr), "r"(rank));
    asm volatile("st.shared::cluster.f32 [%0], %1;" :: "r"(raddr), "f"(v) : "memory");
}

// ---------------- kernel 1: row norms + scalar zeroing ------------------------
__global__ void norms_kernel(const float* __restrict__ ncur, const float* __restrict__ ecur,
                             const float* __restrict__ nnxt, const float* __restrict__ enxt) {
    int gw = blockIdx.x * (blockDim.x >> 5) + (threadIdx.x >> 5);   // row id in [0, 8192)
    int l  = threadIdx.x & 31;
    size_t base = (size_t)gw * D;

    float4 a1 = ((const float4*)(ncur + base))[l];
    float4 a2 = ((const float4*)(ecur + base))[l];
    float4 b1 = ((const float4*)(nnxt + base))[l];
    float4 b2 = ((const float4*)(enxt + base))[l];

    float sa = a1.x*a1.x + a1.y*a1.y + a1.z*a1.z + a1.w*a1.w
             + a2.x*a2.x + a2.y*a2.y + a2.z*a2.z + a2.w*a2.w;
    float sb = b1.x*b1.x + b1.y*b1.y + b1.z*b1.z + b1.w*b1.w
             + b2.x*b2.x + b2.y*b2.y + b2.z*b2.z + b2.w*b2.w;
    sa = wred(sa);
    sb = wred(sb);
    if (l == 0) { g_ra[gw] = sa; g_rb[gw] = sb; }
    if (blockIdx.x == 0 && threadIdx.x < B) { g_qsq[threadIdx.x] = 0.f; g_qsum[threadIdx.x] = 0.f; }
}

// ---------------- kernel 2: gram / cost matrix --------------------------------
// qm[b, j, i] = 0.5*(ra_i + rb_j) - (ncur_i.nnxt_j + ecur_i.enxt_j)
__global__ __launch_bounds__(256) void gram_kernel(
    const float* __restrict__ ncur, const float* __restrict__ ecur,
    const float* __restrict__ nnxt, const float* __restrict__ enxt) {

    __shared__ float Us[64][68];
    __shared__ float Vs[64][68];
    __shared__ float sQred[8];
    __shared__ float sSred[8];

    const int b  = blockIdx.z;
    const int i0 = blockIdx.x * 64;
    const int j0 = blockIdx.y * 64;
    const int tid = threadIdx.x;
    const int tx = tid & 15;
    const int ty = tid >> 4;

    float acc[4][4] = {};

    const int row = tid >> 2;
    const int kq  = tid & 3;

    for (int kc = 0; kc < 4; kc++) {
        const float* usrc = ((kc & 2) ? ecur : ncur) + (size_t)b * (P * D) + (kc & 1) * 64;
        const float* vsrc = ((kc & 2) ? enxt : nnxt) + (size_t)b * (P * D) + (kc & 1) * 64;

        const float4* up = (const float4*)(usrc + (size_t)(i0 + row) * D) + kq * 4;
        const float4* vp = (const float4*)(vsrc + (size_t)(j0 + row) * D) + kq * 4;
        float4 ur[4], vr[4];
        #pragma unroll
        for (int q = 0; q < 4; q++) { ur[q] = up[q]; vr[q] = vp[q]; }

        __syncthreads();
        #pragma unroll
        for (int q = 0; q < 4; q++) {
            int kk = kq * 16 + q * 4;
            Us[kk+0][row] = ur[q].x; Us[kk+1][row] = ur[q].y;
            Us[kk+2][row] = ur[q].z; Us[kk+3][row] = ur[q].w;
            Vs[kk+0][row] = vr[q].x; Vs[kk+1][row] = vr[q].y;
            Vs[kk+2][row] = vr[q].z; Vs[kk+3][row] = vr[q].w;
        }
        __syncthreads();

        #pragma unroll 16
        for (int k = 0; k < 64; k++) {
            float4 u4 = *(const float4*)&Us[k][tx * 4];
            float4 v4 = *(const float4*)&Vs[k][ty * 4];
            float uu[4] = {u4.x, u4.y, u4.z, u4.w};
            float vv[4] = {v4.x, v4.y, v4.z, v4.w};
            #pragma unroll
            for (int r = 0; r < 4; r++)
                #pragma unroll
                for (int c = 0; c < 4; c++)
                    acc[r][c] += vv[r] * uu[c];
        }
    }

    float raL[4], rbL[4];
    #pragma unroll
    for (int c = 0; c < 4; c++) raL[c] = g_ra[b * P + i0 + tx * 4 + c];
    #pragma unroll
    for (int r = 0; r < 4; r++) rbL[r] = g_rb[b * P + j0 + ty * 4 + r];

    float qs = 0.f, q1 = 0.f;
    #pragma unroll
    for (int r = 0; r < 4; r++) {
        float4 o;
        o.x = 0.5f * (raL[0] + rbL[r]) - acc[r][0];
        o.y = 0.5f * (raL[1] + rbL[r]) - acc[r][1];
        o.z = 0.5f * (raL[2] + rbL[r]) - acc[r][2];
        o.w = 0.5f * (raL[3] + rbL[r]) - acc[r][3];
        qs += o.x*o.x + o.y*o.y + o.z*o.z + o.w*o.w;
        q1 += o.x + o.y + o.z + o.w;
        *(float4*)&g_qm[((size_t)b * P + j0 + ty * 4 + r) * P + i0 + tx * 4] = o;
    }
    qs = wred(qs);
    q1 = wred(q1);
    if ((tid & 31) == 0) { sQred[tid >> 5] = qs; sSred[tid >> 5] = q1; }
    __syncthreads();
    if (tid == 0) {
        float t = 0.f, t2 = 0.f;
        #pragma unroll
        for (int w = 0; w < 8; w++) { t += sQred[w]; t2 += sSred[w]; }
        atomicAdd(&g_qsq[b], t);
        atomicAdd(&g_qsum[b], t2);
    }
}

// ---------------- kernel 3: persistent cluster QP solve (single qm pass/iter) --
// cluster of 8 CTAs per batch; each CTA owns 64 rows of X in SMEM.
// Carried s: s_next = sum_c scale_new[c] * T[c], T[c] = sum_j qm[j,c]*Xnorm[j,c]
// Lazy column scaling folded into next iteration's reads.
#define SM_X      0                      // 32768 floats
#define SM_TW     32768                  // 16*512 per-warp T partials
#define SM_CW     (SM_TW + 8192)         // 16*512 per-warp colsum partials
#define SM_SCALE  (SM_CW + 8192)         // 512
#define SM_T      (SM_SCALE + 512)       // 512
#define SM_C      (SM_T + 512)           // 512
#define SM_PART   (SM_C + 512)           // 8
#define SM_RED    (SM_PART + 8)          // 16
#define QP_SMEM_FLOATS (SM_RED + 16)
#define QP_SMEM_BYTES  (QP_SMEM_FLOATS * 4)

__global__ void __cluster_dims__(8, 1, 1) __launch_bounds__(512, 1)
qp_kernel(float* __restrict__ out) {
    extern __shared__ float sm[];
    float4* sX4    = (float4*)(sm + SM_X);
    float4* sTw4   = (float4*)(sm + SM_TW);
    float4* sCw4   = (float4*)(sm + SM_CW);
    float*  sScale = sm + SM_SCALE;
    float4* sSc4   = (float4*)sScale;
    float*  sT     = sm + SM_T;
    float*  sC     = sm + SM_C;
    float*  sPart  = sm + SM_PART;
    float*  sRed   = sm + SM_RED;

    uint32_t rank;
    asm("mov.u32 %0, %%cluster_ctarank;" : "=r"(rank));
    const int b   = blockIdx.x >> 3;
    const int tid = threadIdx.x;
    const int w   = tid >> 5, l = tid & 31;

    const float lr = 0.5f / (g_qsq[b] + 1e-8f);
    float s = g_qsum[b] * (1.f / 512.f);     // s0: X = 1/512, scale = 1
    const float4* qm4 = (const float4*)(g_qm + ((size_t)b * P + rank * 64) * P);

    // init: X = 1/512, scale = 1
    const float4 iv = make_float4(1.f/512, 1.f/512, 1.f/512, 1.f/512);
    for (int idx = tid; idx < 8192; idx += 512) sX4[idx] = iv;
    if (tid < 128) sSc4[tid] = make_float4(1.f, 1.f, 1.f, 1.f);
    __syncthreads();

    const uint32_t sT_a     = smem_u32(sT);
    const uint32_t sC_a     = smem_u32(sC);
    const uint32_t sScale_a = smem_u32(sScale);
    const uint32_t sPart_a  = smem_u32(sPart);

    for (int it = 0; it < ITERS; it++) {
        const float cq = 2.f * lr * s;

        // ---- fused pass over own 64 rows: gradient + clip + row-normalize +
        //      per-column T (qm*Xnorm) and colsum accumulation. ONE qm read.
        float4 tA[4] = {}, cA[4] = {};
        #pragma unroll
        for (int q = 0; q < 4; q++) {
            const int jl = w * 4 + q;
            const float4* qrow = qm4 + jl * 128;
            float4* xrow = sX4 + jl * 128;
            float4 qv[4], vv[4];
            float rs = 0.f;
            #pragma unroll
            for (int t = 0; t < 4; t++) {
                const int c4 = l + 32 * t;
                qv[t] = qrow[c4];                     // L2 (single read per iter)
                float4 x  = xrow[c4];
                float4 sc = sSc4[c4];
                float4 v;
                v.x = fminf(fmaxf(fmaf(-cq, qv[t].x, x.x * sc.x), 0.f), 1.f);
                v.y = fminf(fmaxf(fmaf(-cq, qv[t].y, x.y * sc.y), 0.f), 1.f);
                v.z = fminf(fmaxf(fmaf(-cq, qv[t].z, x.z * sc.z), 0.f), 1.f);
                v.w = fminf(fmaxf(fmaf(-cq, qv[t].w, x.w * sc.w), 0.f), 1.f);
                vv[t] = v;
                rs += v.x + v.y + v.z + v.w;
            }
            rs = wred(rs);
            const float inv = 1.f / (rs + 1e-8f);
            #pragma unroll
            for (int t = 0; t < 4; t++) {
                const int c4 = l + 32 * t;
                float4 v = vv[t];
                v.x *= inv; v.y *= inv; v.z *= inv; v.w *= inv;
                xrow[c4] = v;                         // Xnorm back to SMEM
                tA[t].x += qv[t].x * v.x; tA[t].y += qv[t].y * v.y;
                tA[t].z += qv[t].z * v.z; tA[t].w += qv[t].w * v.w;
                cA[t].x += v.x; cA[t].y += v.y; cA[t].z += v.z; cA[t].w += v.w;
            }
        }
        // per-warp partials to SMEM
        #pragma unroll
        for (int t = 0; t < 4; t++) {
            const int c4 = l + 32 * t;
            sTw4[w * 128 + c4] = tA[t];
            sCw4[w * 128 + c4] = cA[t];
        }
        __syncthreads();

        // ---- CTA-level column totals (2 arrays reduced in parallel)
        if (tid < 256) {
            const int arr = tid >> 7;         // 0 -> T, 1 -> C
            const int c4  = tid & 127;
            const float4* src = (arr ? sCw4 : sTw4) + c4;
            float4 a = make_float4(0.f, 0.f, 0.f, 0.f);
            #pragma unroll
            for (int ww = 0; ww < 16; ww++) {
                float4 vv = src[ww * 128];
                a.x += vv.x; a.y += vv.y; a.z += vv.z; a.w += vv.w;
            }
            ((float4*)(arr ? sC : sT))[c4] = a;
        }
        cluster_sync_all();                   // #1

        // ---- phase B: this CTA owns columns [rank*64, rank*64+64)
        {
            const int sub  = tid & 7;         // which rank to read
            const int colh = tid >> 3;        // 0..63
            const int col  = (int)rank * 64 + colh;
            float tR = dsmem_ld_f32(sT_a + (uint32_t)col * 4, (uint32_t)sub);
            float cR = dsmem_ld_f32(sC_a + (uint32_t)col * 4, (uint32_t)sub);
            #pragma unroll
            for (int o = 1; o <= 4; o <<= 1) {
                tR += __shfl_xor_sync(0xffffffffu, tR, o);
                cR += __shfl_xor_sync(0xffffffffu, cR, o);
            }
            const float scl = fminf(1.f, 2.f / (cR + 1e-8f));
            dsmem_st_f32(sScale_a + (uint32_t)col * 4, (uint32_t)sub, scl); // scatter to all ranks
            float contrib = (sub == 0) ? scl * tR : 0.f;
            contrib = wred(contrib);          // warp covers 4 columns
            if (l == 0) sRed[w] = contrib;
        }
        __syncthreads();
        if (w == 0) {
            float v = (l < 16) ? sRed[l] : 0.f;
            v = wred(v);                      // this CTA's s-partial (64 cols)
            if (l < 8) dsmem_st_f32(sPart_a + rank * 4, (uint32_t)l, v);
        }
        cluster_sync_all();                   // #2

        s = sPart[0] + sPart[1] + sPart[2] + sPart[3]
          + sPart[4] + sPart[5] + sPart[6] + sPart[7];
    }

    // ---- writeout: apply final lazy col scale
    float4* out4 = (float4*)out + ((size_t)b * P + rank * 64) * 128;
    for (int idx = tid; idx < 8192; idx += 512) {
        float4 x = sX4[idx], sc = sSc4[idx & 127];
        out4[idx] = make_float4(x.x * sc.x, x.y * sc.y, x.z * sc.z, x.w * sc.w);
    }
}

// ---------------- launch -------------------------------------------------------
extern "C" void kernel_launch(void* const* d_in, const int* in_sizes, int n_in,
                              void* d_out, int out_size) {
    (void)in_sizes; (void)n_in; (void)out_size;
    const float* ncur = (const float*)d_in[0];
    const float* ecur = (const float*)d_in[1];
    const float* nnxt = (const float*)d_in[2];
    const float* enxt = (const float*)d_in[3];
    float* out = (float*)d_out;

    cudaFuncSetAttribute(qp_kernel, cudaFuncAttributeMaxDynamicSharedMemorySize, QP_SMEM_BYTES);

    norms_kernel<<<1024, 256>>>(ncur, ecur, nnxt, enxt);
    gram_kernel<<<dim3(8, 8, B), 256>>>(ncur, ecur, nnxt, enxt);
    qp_kernel<<<128, 512, QP_SMEM_BYTES>>>(out);
}

// round 4
// speedup vs baseline: 1.7011x; 1.6108x over previous
#include <cuda_runtime.h>
#include <cstdint>

#define B 16
#define P 512          // m = n = 512
#define D 128
#define ITERS 20

// ---------------- device scratch (allocation-free rule: __device__ globals) --
__device__ float g_qm[(size_t)B * P * P];   // 16 MB, (b, j, i) row-major, i contiguous
__device__ float g_ra[B * P];               // ||u_i||^2 (cur)
__device__ float g_rb[B * P];               // ||v_j||^2 (nxt)
__device__ float g_qsq[B];                  // sum qm^2 per batch (for lr)
__device__ float g_qsum[B];                 // sum qm per batch (for s0)
// double-buffered per-rank partials: [buf][b][rank][ T[512] | C[512] ]
__device__ float g_part[2 * B * 8 * 1024];
__device__ unsigned g_qpbar[B];             // per-batch arrival counter

// ---------------- helpers ----------------------------------------------------
__device__ __forceinline__ float wred(float v) {
    v += __shfl_xor_sync(0xffffffffu, v, 16);
    v += __shfl_xor_sync(0xffffffffu, v, 8);
    v += __shfl_xor_sync(0xffffffffu, v, 4);
    v += __shfl_xor_sync(0xffffffffu, v, 2);
    v += __shfl_xor_sync(0xffffffffu, v, 1);
    return v;
}

// ---------------- kernel 1: row norms + scalar zeroing ------------------------
__global__ void norms_kernel(const float* __restrict__ ncur, const float* __restrict__ ecur,
                             const float* __restrict__ nnxt, const float* __restrict__ enxt) {
    int gw = blockIdx.x * (blockDim.x >> 5) + (threadIdx.x >> 5);   // row id in [0, 8192)
    int l  = threadIdx.x & 31;
    size_t base = (size_t)gw * D;

    float4 a1 = ((const float4*)(ncur + base))[l];
    float4 a2 = ((const float4*)(ecur + base))[l];
    float4 b1 = ((const float4*)(nnxt + base))[l];
    float4 b2 = ((const float4*)(enxt + base))[l];

    float sa = a1.x*a1.x + a1.y*a1.y + a1.z*a1.z + a1.w*a1.w
             + a2.x*a2.x + a2.y*a2.y + a2.z*a2.z + a2.w*a2.w;
    float sb = b1.x*b1.x + b1.y*b1.y + b1.z*b1.z + b1.w*b1.w
             + b2.x*b2.x + b2.y*b2.y + b2.z*b2.z + b2.w*b2.w;
    sa = wred(sa);
    sb = wred(sb);
    if (l == 0) { g_ra[gw] = sa; g_rb[gw] = sb; }
    if (blockIdx.x == 0 && threadIdx.x < B) {
        g_qsq[threadIdx.x] = 0.f; g_qsum[threadIdx.x] = 0.f; g_qpbar[threadIdx.x] = 0u;
    }
}

// ---------------- kernel 2: gram / cost matrix --------------------------------
// qm[b, j, i] = 0.5*(ra_i + rb_j) - (ncur_i.nnxt_j + ecur_i.enxt_j)
__global__ __launch_bounds__(256) void gram_kernel(
    const float* __restrict__ ncur, const float* __restrict__ ecur,
    const float* __restrict__ nnxt, const float* __restrict__ enxt) {

    __shared__ float Us[64][68];
    __shared__ float Vs[64][68];
    __shared__ float sQred[8];
    __shared__ float sSred[8];

    const int b  = blockIdx.z;
    const int i0 = blockIdx.x * 64;
    const int j0 = blockIdx.y * 64;
    const int tid = threadIdx.x;
    const int tx = tid & 15;
    const int ty = tid >> 4;

    float acc[4][4] = {};

    const int row = tid >> 2;
    const int kq  = tid & 3;

    for (int kc = 0; kc < 4; kc++) {
        const float* usrc = ((kc & 2) ? ecur : ncur) + (size_t)b * (P * D) + (kc & 1) * 64;
        const float* vsrc = ((kc & 2) ? enxt : nnxt) + (size_t)b * (P * D) + (kc & 1) * 64;

        const float4* up = (const float4*)(usrc + (size_t)(i0 + row) * D) + kq * 4;
        const float4* vp = (const float4*)(vsrc + (size_t)(j0 + row) * D) + kq * 4;
        float4 ur[4], vr[4];
        #pragma unroll
        for (int q = 0; q < 4; q++) { ur[q] = up[q]; vr[q] = vp[q]; }

        __syncthreads();
        #pragma unroll
        for (int q = 0; q < 4; q++) {
            int kk = kq * 16 + q * 4;
            Us[kk+0][row] = ur[q].x; Us[kk+1][row] = ur[q].y;
            Us[kk+2][row] = ur[q].z; Us[kk+3][row] = ur[q].w;
            Vs[kk+0][row] = vr[q].x; Vs[kk+1][row] = vr[q].y;
            Vs[kk+2][row] = vr[q].z; Vs[kk+3][row] = vr[q].w;
        }
        __syncthreads();

        #pragma unroll 16
        for (int k = 0; k < 64; k++) {
            float4 u4 = *(const float4*)&Us[k][tx * 4];
            float4 v4 = *(const float4*)&Vs[k][ty * 4];
            float uu[4] = {u4.x, u4.y, u4.z, u4.w};
            float vv[4] = {v4.x, v4.y, v4.z, v4.w};
            #pragma unroll
            for (int r = 0; r < 4; r++)
                #pragma unroll
                for (int c = 0; c < 4; c++)
                    acc[r][c] += vv[r] * uu[c];
        }
    }

    float raL[4], rbL[4];
    #pragma unroll
    for (int c = 0; c < 4; c++) raL[c] = g_ra[b * P + i0 + tx * 4 + c];
    #pragma unroll
    for (int r = 0; r < 4; r++) rbL[r] = g_rb[b * P + j0 + ty * 4 + r];

    float qs = 0.f, q1 = 0.f;
    #pragma unroll
    for (int r = 0; r < 4; r++) {
        float4 o;
        o.x = 0.5f * (raL[0] + rbL[r]) - acc[r][0];
        o.y = 0.5f * (raL[1] + rbL[r]) - acc[r][1];
        o.z = 0.5f * (raL[2] + rbL[r]) - acc[r][2];
        o.w = 0.5f * (raL[3] + rbL[r]) - acc[r][3];
        qs += o.x*o.x + o.y*o.y + o.z*o.z + o.w*o.w;
        q1 += o.x + o.y + o.z + o.w;
        *(float4*)&g_qm[((size_t)b * P + j0 + ty * 4 + r) * P + i0 + tx * 4] = o;
    }
    qs = wred(qs);
    q1 = wred(q1);
    if ((tid & 31) == 0) { sQred[tid >> 5] = qs; sSred[tid >> 5] = q1; }
    __syncthreads();
    if (tid == 0) {
        float t = 0.f, t2 = 0.f;
        #pragma unroll
        for (int w = 0; w < 8; w++) { t += sQred[w]; t2 += sSred[w]; }
        atomicAdd(&g_qsq[b], t);
        atomicAdd(&g_qsum[b], t2);
    }
}

// ---------------- kernel 3: persistent QP solve, NO clusters -------------------
// 128 plain CTAs (8 per batch), each owns 64 rows of X in SMEM. Cross-CTA data
// (column T/C partials) goes through L2 (.cg) with a release/acquire counter
// barrier; every CTA redundantly computes all 512 column scales + scalar s,
// so only ONE global barrier per iteration and no second distribution step.
#define SM_X      0                      // 32768 floats
#define SM_TW     32768                  // 16*512 per-warp T partials
#define SM_CW     (SM_TW + 8192)         // 16*512 per-warp colsum partials
#define SM_SCALE  (SM_CW + 8192)         // 512 (col scale, lazy)
#define SM_RED    (SM_SCALE + 512)       // 16
#define SM_S      (SM_RED + 16)          // 4
#define QP_SMEM_FLOATS (SM_S + 4)
#define QP_SMEM_BYTES  (QP_SMEM_FLOATS * 4)

__global__ void __launch_bounds__(512, 1)
qp_kernel(float* __restrict__ out) {
    extern __shared__ float sm[];
    float4* sX4    = (float4*)(sm + SM_X);
    float4* sTw4   = (float4*)(sm + SM_TW);
    float4* sCw4   = (float4*)(sm + SM_CW);
    float*  sScale = sm + SM_SCALE;
    float4* sSc4   = (float4*)sScale;
    float*  sRed   = sm + SM_RED;
    float*  sS     = sm + SM_S;

    const int b    = blockIdx.x >> 3;
    const int rank = blockIdx.x & 7;
    const int tid  = threadIdx.x;
    const int w    = tid >> 5, l = tid & 31;

    const float lr = 0.5f / (g_qsq[b] + 1e-8f);
    float s = g_qsum[b] * (1.f / 512.f);     // s0: X = 1/512, scale = 1
    const float4* qm4 = (const float4*)(g_qm + ((size_t)b * P + rank * 64) * P);

    // init: X = 1/512, scale = 1
    const float4 iv = make_float4(1.f/512, 1.f/512, 1.f/512, 1.f/512);
    for (int idx = tid; idx < 8192; idx += 512) sX4[idx] = iv;
    if (tid < 128) sSc4[tid] = make_float4(1.f, 1.f, 1.f, 1.f);
    __syncthreads();

    for (int it = 0; it < ITERS; it++) {
        const float cq = 2.f * lr * s;

        // ---- phase A: gradient + clip + row-normalize + per-column T/C partials
        //      (single qm read per iteration)
        float4 tA[4] = {}, cA[4] = {};
        #pragma unroll
        for (int q = 0; q < 4; q++) {
            const int jl = w * 4 + q;
            const float4* qrow = qm4 + jl * 128;
            float4* xrow = sX4 + jl * 128;
            float4 qv[4], vv[4];
            float rs = 0.f;
            #pragma unroll
            for (int t = 0; t < 4; t++) {
                const int c4 = l + 32 * t;
                qv[t] = qrow[c4];                     // L2
                float4 x  = xrow[c4];
                float4 sc = sSc4[c4];
                float4 v;
                v.x = fminf(fmaxf(fmaf(-cq, qv[t].x, x.x * sc.x), 0.f), 1.f);
                v.y = fminf(fmaxf(fmaf(-cq, qv[t].y, x.y * sc.y), 0.f), 1.f);
                v.z = fminf(fmaxf(fmaf(-cq, qv[t].z, x.z * sc.z), 0.f), 1.f);
                v.w = fminf(fmaxf(fmaf(-cq, qv[t].w, x.w * sc.w), 0.f), 1.f);
                vv[t] = v;
                rs += v.x + v.y + v.z + v.w;
            }
            rs = wred(rs);
            const float inv = 1.f / (rs + 1e-8f);
            #pragma unroll
            for (int t = 0; t < 4; t++) {
                const int c4 = l + 32 * t;
                float4 v = vv[t];
                v.x *= inv; v.y *= inv; v.z *= inv; v.w *= inv;
                xrow[c4] = v;                         // Xnorm back to SMEM
                tA[t].x += qv[t].x * v.x; tA[t].y += qv[t].y * v.y;
                tA[t].z += qv[t].z * v.z; tA[t].w += qv[t].w * v.w;
                cA[t].x += v.x; cA[t].y += v.y; cA[t].z += v.z; cA[t].w += v.w;
            }
        }
        #pragma unroll
        for (int t = 0; t < 4; t++) {
            const int c4 = l + 32 * t;
            sTw4[w * 128 + c4] = tA[t];
            sCw4[w * 128 + c4] = cA[t];
        }
        __syncthreads();

        // ---- CTA-level column totals -> global partial slot (L2, .cg)
        const int buf = it & 1;
        float* gslot = g_part + ((size_t)buf * B + b) * 8192 + rank * 1024;
        if (tid < 256) {
            const int arr = tid >> 7;         // 0 -> T, 1 -> C
            const int c4  = tid & 127;
            const float4* src = (arr ? sCw4 : sTw4) + c4;
            float4 a = make_float4(0.f, 0.f, 0.f, 0.f);
            #pragma unroll
            for (int ww = 0; ww < 16; ww++) {
                float4 vv = src[ww * 128];
                a.x += vv.x; a.y += vv.y; a.z += vv.z; a.w += vv.w;
            }
            __stcg((float4*)(gslot + arr * 512) + c4, a);
        }
        __threadfence();
        __syncthreads();

        // ---- single global barrier per batch (release arrive, acquire spin)
        if (tid == 0) {
            asm volatile("red.release.gpu.global.add.u32 [%0], %1;"
                         :: "l"(&g_qpbar[b]), "r"(1u) : "memory");
            const unsigned target = 8u * (unsigned)(it + 1);
            unsigned v;
            do {
                asm volatile("ld.acquire.gpu.global.u32 %0, [%1];"
                             : "=r"(v) : "l"(&g_qpbar[b]) : "memory");
                if (v >= target) break;
                __nanosleep(64);
            } while (true);
        }
        __syncthreads();

        // ---- phase B (redundant per CTA): col scale for ALL 512 cols + scalar s
        {
            const float* pb = g_part + ((size_t)buf * B + b) * 8192;
            float Tt = 0.f, Ct = 0.f;
            #pragma unroll
            for (int r = 0; r < 8; r++) {
                Tt += __ldcg(pb + r * 1024 + tid);
                Ct += __ldcg(pb + r * 1024 + 512 + tid);
            }
            const float scl = fminf(1.f, 2.f / (Ct + 1e-8f));
            sScale[tid] = scl;
            float contrib = wred(scl * Tt);
            if (l == 0) sRed[w] = contrib;
        }
        __syncthreads();
        if (tid < 32) {
            float v = (tid < 16) ? sRed[tid] : 0.f;
            v = wred(v);
            if (tid == 0) sS[0] = v;
        }
        __syncthreads();
        s = sS[0];
    }

    // ---- writeout: apply final lazy col scale
    float4* out4 = (float4*)out + ((size_t)b * P + rank * 64) * 128;
    for (int idx = tid; idx < 8192; idx += 512) {
        float4 x = sX4[idx], sc = sSc4[idx & 127];
        out4[idx] = make_float4(x.x * sc.x, x.y * sc.y, x.z * sc.z, x.w * sc.w);
    }
}

// ---------------- launch -------------------------------------------------------
extern "C" void kernel_launch(void* const* d_in, const int* in_sizes, int n_in,
                              void* d_out, int out_size) {
    (void)in_sizes; (void)n_in; (void)out_size;
    const float* ncur = (const float*)d_in[0];
    const float* ecur = (const float*)d_in[1];
    const float* nnxt = (const float*)d_in[2];
    const float* enxt = (const float*)d_in[3];
    float* out = (float*)d_out;

    cudaFuncSetAttribute(qp_kernel, cudaFuncAttributeMaxDynamicSharedMemorySize, QP_SMEM_BYTES);

    norms_kernel<<<1024, 256>>>(ncur, ecur, nnxt, enxt);
    gram_kernel<<<dim3(8, 8, B), 256>>>(ncur, ecur, nnxt, enxt);
    qp_kernel<<<128, 512, QP_SMEM_BYTES>>>(out);
}